// round 5
// baseline (speedup 1.0000x reference)
#include <cuda_runtime.h>

typedef unsigned long long u64;

// ---------- packed f32x2 helpers (sm_103a FFMA2 only via PTX) ----------
__device__ __forceinline__ u64 pack2(float lo, float hi){
    u64 r; asm("mov.b64 %0, {%1,%2};" : "=l"(r) : "f"(lo), "f"(hi)); return r;
}
__device__ __forceinline__ void unpack2(u64 v, float &lo, float &hi){
    asm("mov.b64 {%0,%1}, %2;" : "=f"(lo), "=f"(hi) : "l"(v));
}
__device__ __forceinline__ u64 mul2(u64 a, u64 b){
    u64 r; asm("mul.rn.f32x2 %0, %1, %2;" : "=l"(r) : "l"(a), "l"(b)); return r;
}
__device__ __forceinline__ void fma2(u64 &d, u64 a, u64 b){
    asm("fma.rn.f32x2 %0, %1, %2, %0;" : "+l"(d) : "l"(a), "l"(b));
}

// ---------- symmetrized coefficient tables (written by prep each launch) ----
// Duplicated {c,c} pairs; row strides are multiples of 16B for LDS.128.
__device__ __align__(16) u64 g_C1[9 * 4];      // deg-1: 9 monos x 4 cols
__device__ __align__(16) u64 g_C2[45 * 8];     // deg-2: 45 monos x 8 cols
__device__ __align__(16) u64 g_C3[165 * 12];   // deg-3: 165 monos x 12 cols

__device__ __forceinline__ float fetch3(const float* __restrict__ b30,
                                        const float* __restrict__ b31,
                                        int i, int j, int k, int c){
    int base = ((i * 9 + j) * 9 + k) * 3;         // b30: (9,9,9,3,1); b31: (9,9,9,3,3)
    if (c < 3) return b30[base + c];
    return b31[base * 3 + (c - 3)];
}

__global__ void prep_kernel(const float* __restrict__ b10, const float* __restrict__ b11,
                            const float* __restrict__ b20, const float* __restrict__ b21,
                            const float* __restrict__ b30, const float* __restrict__ b31){
    int tid = blockIdx.x * blockDim.x + threadIdx.x;

    // ---- deg-1: tasks [0, 36) ----
    if (tid < 36){
        int a = tid >> 2, c = tid & 3;
        float v = (c == 0) ? b10[a] : b11[a * 3 + c - 1];
        g_C1[tid] = pack2(v, v);
    }

    // ---- deg-2: tasks [64, 64+360) ----
    int t2 = tid - 64;
    if (t2 >= 0 && t2 < 45 * 8){
        int mono = t2 >> 3, c = t2 & 7;
        int a = 0, rem = mono;
        while (rem >= 9 - a){ rem -= 9 - a; a++; }
        int b = a + rem;                            // a <= b
        float v;
        if (c < 2){                                 // b20: (9,9,2,1)
            v = b20[(a * 9 + b) * 2 + c];
            if (a != b) v += b20[(b * 9 + a) * 2 + c];
        } else {                                    // b21: (9,9,2,3); c-2 = s*3+p
            int sp = c - 2;
            v = b21[(a * 9 + b) * 6 + sp];
            if (a != b) v += b21[(b * 9 + a) * 6 + sp];
        }
        g_C2[t2] = pack2(v, v);
    }

    // ---- deg-3: tasks [448, 448+1980) ----
    int t3 = tid - 448;
    if (t3 >= 0 && t3 < 165 * 12){
        int mono = t3 / 12, c = t3 % 12;
        int a = 0, rem = mono;
        while (true){ int cnt = (9 - a) * (10 - a) / 2; if (rem < cnt) break; rem -= cnt; a++; }
        int b = a;
        while (rem >= 9 - b){ rem -= 9 - b; b++; }
        int k = b + rem;                            // a <= b <= k
        float v = fetch3(b30, b31, a, b, k, c);
        if (a == b && b == k){
            // single permutation
        } else if (a == b){                         // (a,a,k): 3 perms
            v += fetch3(b30, b31, a, k, b, c) + fetch3(b30, b31, k, a, b, c);
        } else if (b == k){                         // (a,b,b): 3 perms
            v += fetch3(b30, b31, b, a, k, c) + fetch3(b30, b31, b, k, a, c);
        } else {                                    // all distinct: 6 perms
            v += fetch3(b30, b31, a, k, b, c) + fetch3(b30, b31, b, a, k, c)
               + fetch3(b30, b31, b, k, a, c) + fetch3(b30, b31, k, a, b, c)
               + fetch3(b30, b31, k, b, a, c);
        }
        g_C3[t3] = pack2(v, v);
    }
}

// ---------- main kernel: 1 block = 2 nodes, 128 threads, 2 channels/thread --
// Two passes over output-column halves -> only 12 moment accumulators live.
__global__ void __launch_bounds__(128, 6) mace_kernel(
    const float* __restrict__ nf, const int* __restrict__ species,
    const float* __restrict__ w10, const float* __restrict__ w11,
    const float* __restrict__ w20, const float* __restrict__ w21,
    const float* __restrict__ w30, const float* __restrict__ w31,
    float* __restrict__ out)
{
    __shared__ __align__(16) u64 sC1[9 * 4];
    __shared__ __align__(16) u64 sC2[45 * 8];
    __shared__ __align__(16) u64 sC3[165 * 12];

    const int t = threadIdx.x;
    for (int i = t; i < 36;   i += 128) sC1[i] = g_C1[i];
    for (int i = t; i < 360;  i += 128) sC2[i] = g_C2[i];
    for (int i = t; i < 1980; i += 128) sC3[i] = g_C3[i];
    __syncthreads();

    const int node = blockIdx.x * 2 + (t >> 6);
    const int tl   = t & 63;
    const int m0   = tl * 2;                 // this thread's channel pair
    const float* nfp = nf + (size_t)node * 1152;

    // x components (2 channels packed) fully in registers.
    // layout: [0,128)=l0, [128,512)=l1 (mul-major dim3), [512,1152)=l2 (dim5)
    u64 x[9];
    {
        float2 v = *(const float2*)(nfp + m0);
        x[0] = pack2(v.x, v.y);
    }
    #pragma unroll
    for (int j = 0; j < 3; j++)
        x[1 + j] = pack2(nfp[128 + m0 * 3 + j], nfp[128 + m0 * 3 + 3 + j]);
    #pragma unroll
    for (int j = 0; j < 5; j++)
        x[4 + j] = pack2(nfp[512 + m0 * 5 + j], nfp[512 + m0 * 5 + 5 + j]);

    const int sp = species[node];
    const float* W10 = w10 + sp * 128 + m0;
    const float* W11 = w11 + sp * 128 + m0;
    const float* W20 = w20 + sp * 256 + m0;
    const float* W21 = w21 + sp * 256 + m0;
    const float* W30 = w30 + sp * 384 + m0;
    const float* W31 = w31 + sp * 384 + m0;

    // Output accumulators (held across both passes).
    u64 O0 = 0ull, OP0 = 0ull, OP1 = 0ull, OP2 = 0ull;

    #pragma unroll
    for (int pass = 0; pass < 2; pass++){
        // Pass accumulators: P[0..1]=C1 cols, P[2..5]=C2 cols, P[6..11]=C3 cols
        u64 P[12];
        #pragma unroll
        for (int i = 0; i < 12; i++) P[i] = 0ull;

        int i2 = 0, i3 = 0;                  // constant-folded by full unroll
        #pragma unroll
        for (int a = 0; a < 9; a++){
            {
                ulonglong2 cp = *(const ulonglong2*)(sC1 + a * 4 + pass * 2);
                fma2(P[0], cp.x, x[a]);
                fma2(P[1], cp.y, x[a]);
            }
            #pragma unroll
            for (int b = a; b < 9; b++){
                u64 pab = mul2(x[a], x[b]);
                #pragma unroll
                for (int c = 0; c < 2; c++){
                    ulonglong2 cp = *(const ulonglong2*)(sC2 + i2 * 8 + pass * 4 + 2 * c);
                    fma2(P[2 + 2 * c], cp.x, pab);
                    fma2(P[3 + 2 * c], cp.y, pab);
                }
                i2++;
                #pragma unroll
                for (int k = b; k < 9; k++){
                    u64 p3 = mul2(pab, x[k]);
                    #pragma unroll
                    for (int c = 0; c < 3; c++){
                        ulonglong2 cp = *(const ulonglong2*)(sC3 + i3 * 12 + pass * 6 + 2 * c);
                        fma2(P[6 + 2 * c], cp.x, p3);
                        fma2(P[7 + 2 * c], cp.y, p3);
                    }
                    i3++;
                }
            }
        }

        if (pass == 0){
            // C1: c0=b10 s0 -> O0 ; c1=b11 p0 -> OP0
            fma2(O0,  *(const u64*)(W10),       P[0]);
            fma2(OP0, *(const u64*)(W11),       P[1]);
            // C2 cols 0..3: b20 s0,s1 -> O0 ; b21 s0p0 -> OP0 ; s0p1 -> OP1
            fma2(O0,  *(const u64*)(W20),       P[2]);
            fma2(O0,  *(const u64*)(W20 + 128), P[3]);
            fma2(OP0, *(const u64*)(W21),       P[4]);
            fma2(OP1, *(const u64*)(W21),       P[5]);
            // C3 cols 0..5: b30 s0..2 -> O0 ; b31 s0 p0..2 -> OP0..2
            fma2(O0,  *(const u64*)(W30),       P[6]);
            fma2(O0,  *(const u64*)(W30 + 128), P[7]);
            fma2(O0,  *(const u64*)(W30 + 256), P[8]);
            fma2(OP0, *(const u64*)(W31),       P[9]);
            fma2(OP1, *(const u64*)(W31),       P[10]);
            fma2(OP2, *(const u64*)(W31),       P[11]);
        } else {
            // C1 cols 2,3: b11 p1,p2 -> OP1, OP2
            fma2(OP1, *(const u64*)(W11),       P[0]);
            fma2(OP2, *(const u64*)(W11),       P[1]);
            // C2 cols 4..7: s0p2 -> OP2 (w21 s0); s1p0..2 -> OP0..2 (w21 s1)
            fma2(OP2, *(const u64*)(W21),       P[2]);
            fma2(OP0, *(const u64*)(W21 + 128), P[3]);
            fma2(OP1, *(const u64*)(W21 + 128), P[4]);
            fma2(OP2, *(const u64*)(W21 + 128), P[5]);
            // C3 cols 6..11: s1 p0..2 -> OP0..2 (w31 s1); s2 p0..2 -> OP0..2 (w31 s2)
            fma2(OP0, *(const u64*)(W31 + 128), P[6]);
            fma2(OP1, *(const u64*)(W31 + 128), P[7]);
            fma2(OP2, *(const u64*)(W31 + 128), P[8]);
            fma2(OP0, *(const u64*)(W31 + 256), P[9]);
            fma2(OP1, *(const u64*)(W31 + 256), P[10]);
            fma2(OP2, *(const u64*)(W31 + 256), P[11]);
        }
    }

    float* outp = out + (size_t)node * 512;
    {
        float lo, hi; unpack2(O0, lo, hi);
        *(float2*)(outp + m0) = make_float2(lo, hi);     // out slice 0: [0,128)
    }
    {
        float lo, hi;
        unpack2(OP0, lo, hi);
        outp[128 + m0 * 3 + 0] = lo;  outp[128 + m0 * 3 + 3] = hi;
        unpack2(OP1, lo, hi);
        outp[128 + m0 * 3 + 1] = lo;  outp[128 + m0 * 3 + 4] = hi;
        unpack2(OP2, lo, hi);
        outp[128 + m0 * 3 + 2] = lo;  outp[128 + m0 * 3 + 5] = hi;
    }
}

extern "C" void kernel_launch(void* const* d_in, const int* in_sizes, int n_in,
                              void* d_out, int out_size){
    // metadata order is INTERLEAVED (b_i, w_i) pairs.
    const float* nf      = (const float*)d_in[0];
    const int*   species = (const int*)  d_in[1];
    const float* b10 = (const float*)d_in[2];
    const float* w10 = (const float*)d_in[3];
    const float* b11 = (const float*)d_in[4];
    const float* w11 = (const float*)d_in[5];
    const float* b20 = (const float*)d_in[6];
    const float* w20 = (const float*)d_in[7];
    const float* b21 = (const float*)d_in[8];
    const float* w21 = (const float*)d_in[9];
    const float* b30 = (const float*)d_in[10];
    const float* w30 = (const float*)d_in[11];
    const float* b31 = (const float*)d_in[12];
    const float* w31 = (const float*)d_in[13];

    const int n_nodes = in_sizes[1];   // species element count (2048, even)

    prep_kernel<<<19, 128>>>(b10, b11, b20, b21, b30, b31);
    // 1 block = 2 nodes, 64 threads/node, 2 channels/thread, two column passes
    mace_kernel<<<n_nodes / 2, 128>>>(nf, species, w10, w11, w20, w21, w30, w31,
                                      (float*)d_out);
}

// round 6
// speedup vs baseline: 6.2688x; 6.2688x over previous
#include <cuda_runtime.h>

typedef unsigned long long u64;

// ---------- packed f32x2 helpers (sm_103a FFMA2 only via PTX) ----------
__device__ __forceinline__ u64 pack2(float lo, float hi){
    u64 r; asm("mov.b64 %0, {%1,%2};" : "=l"(r) : "f"(lo), "f"(hi)); return r;
}
__device__ __forceinline__ void unpack2(u64 v, float &lo, float &hi){
    asm("mov.b64 {%0,%1}, %2;" : "=f"(lo), "=f"(hi) : "l"(v));
}
__device__ __forceinline__ u64 mul2(u64 a, u64 b){
    u64 r; asm("mul.rn.f32x2 %0, %1, %2;" : "=l"(r) : "l"(a), "l"(b)); return r;
}
__device__ __forceinline__ void fma2(u64 &d, u64 a, u64 b){
    asm("fma.rn.f32x2 %0, %1, %2, %0;" : "+l"(d) : "l"(a), "l"(b));
}

// ---------- symmetrized coefficient tables (written by prep each launch) ----
// Duplicated {c,c} pairs; row strides are multiples of 16B for LDS.128.
__device__ __align__(16) u64 g_C1[9 * 4];      // deg-1: 9 monos x 4 cols
__device__ __align__(16) u64 g_C2[45 * 8];     // deg-2: 45 monos x 8 cols
__device__ __align__(16) u64 g_C3[165 * 12];   // deg-3: 165 monos x 12 cols

__device__ __forceinline__ float fetch3(const float* __restrict__ b30,
                                        const float* __restrict__ b31,
                                        int i, int j, int k, int c){
    int base = ((i * 9 + j) * 9 + k) * 3;         // b30: (9,9,9,3,1); b31: (9,9,9,3,3)
    if (c < 3) return b30[base + c];
    return b31[base * 3 + (c - 3)];
}

__global__ void prep_kernel(const float* __restrict__ b10, const float* __restrict__ b11,
                            const float* __restrict__ b20, const float* __restrict__ b21,
                            const float* __restrict__ b30, const float* __restrict__ b31){
    int tid = blockIdx.x * blockDim.x + threadIdx.x;

    // ---- deg-1: tasks [0, 36) ----
    if (tid < 36){
        int a = tid >> 2, c = tid & 3;
        float v = (c == 0) ? b10[a] : b11[a * 3 + c - 1];
        g_C1[tid] = pack2(v, v);
    }

    // ---- deg-2: tasks [64, 64+360) ----
    int t2 = tid - 64;
    if (t2 >= 0 && t2 < 45 * 8){
        int mono = t2 >> 3, c = t2 & 7;
        int a = 0, rem = mono;
        while (rem >= 9 - a){ rem -= 9 - a; a++; }
        int b = a + rem;                            // a <= b
        float v;
        if (c < 2){                                 // b20: (9,9,2,1)
            v = b20[(a * 9 + b) * 2 + c];
            if (a != b) v += b20[(b * 9 + a) * 2 + c];
        } else {                                    // b21: (9,9,2,3); c-2 = s*3+p
            int sp = c - 2;
            v = b21[(a * 9 + b) * 6 + sp];
            if (a != b) v += b21[(b * 9 + a) * 6 + sp];
        }
        g_C2[t2] = pack2(v, v);
    }

    // ---- deg-3: tasks [448, 448+1980) ----
    int t3 = tid - 448;
    if (t3 >= 0 && t3 < 165 * 12){
        int mono = t3 / 12, c = t3 % 12;
        int a = 0, rem = mono;
        while (true){ int cnt = (9 - a) * (10 - a) / 2; if (rem < cnt) break; rem -= cnt; a++; }
        int b = a;
        while (rem >= 9 - b){ rem -= 9 - b; b++; }
        int k = b + rem;                            // a <= b <= k
        float v = fetch3(b30, b31, a, b, k, c);
        if (a == b && b == k){
            // single permutation
        } else if (a == b){                         // (a,a,k): 3 perms
            v += fetch3(b30, b31, a, k, b, c) + fetch3(b30, b31, k, a, b, c);
        } else if (b == k){                         // (a,b,b): 3 perms
            v += fetch3(b30, b31, b, a, k, c) + fetch3(b30, b31, b, k, a, c);
        } else {                                    // all distinct: 6 perms
            v += fetch3(b30, b31, a, k, b, c) + fetch3(b30, b31, b, a, k, c)
               + fetch3(b30, b31, b, k, a, c) + fetch3(b30, b31, k, a, b, c)
               + fetch3(b30, b31, k, b, a, c);
        }
        g_C3[t3] = pack2(v, v);
    }
}

// ---------- main kernel: 1 block = 2 nodes, 64 threads, 4 channels/thread ---
// __launch_bounds__(64, 5): 204-reg cap so ptxas can hoist coefficient LDS.128s
// ~4 iterations ahead of their consumers (29-cyc LDS latency hiding).
__global__ void __launch_bounds__(64, 5) mace_kernel(
    const float* __restrict__ nf, const int* __restrict__ species,
    const float* __restrict__ w10, const float* __restrict__ w11,
    const float* __restrict__ w20, const float* __restrict__ w21,
    const float* __restrict__ w30, const float* __restrict__ w31,
    float* __restrict__ out)
{
    __shared__ __align__(16) u64 sC1[9 * 4];
    __shared__ __align__(16) u64 sC2[45 * 8];
    __shared__ __align__(16) u64 sC3[165 * 12];

    const int t = threadIdx.x;
    for (int i = t; i < 36;   i += 64) sC1[i] = g_C1[i];
    for (int i = t; i < 360;  i += 64) sC2[i] = g_C2[i];
    for (int i = t; i < 1980; i += 64) sC3[i] = g_C3[i];
    __syncthreads();

    const int node = blockIdx.x * 2 + (t >> 5);
    const int tl   = t & 31;
    const int m0   = tl * 4;                 // channels m0..m0+3 (A pair, B pair)
    const float* nfp = nf + (size_t)node * 1152;

    // x components fully in registers.
    // layout: [0,128)=l0, [128,512)=l1 (mul-major dim3), [512,1152)=l2 (dim5)
    u64 xA[9], xB[9];
    {
        float4 v = *(const float4*)(nfp + m0);   // m0 % 4 == 0 -> 16B aligned
        xA[0] = pack2(v.x, v.y);
        xB[0] = pack2(v.z, v.w);
    }
    #pragma unroll
    for (int j = 0; j < 3; j++){
        xA[1 + j] = pack2(nfp[128 + m0 * 3 + j],      nfp[128 + m0 * 3 + 3 + j]);
        xB[1 + j] = pack2(nfp[128 + m0 * 3 + 6 + j],  nfp[128 + m0 * 3 + 9 + j]);
    }
    #pragma unroll
    for (int j = 0; j < 5; j++){
        xA[4 + j] = pack2(nfp[512 + m0 * 5 + j],      nfp[512 + m0 * 5 + 5 + j]);
        xB[4 + j] = pack2(nfp[512 + m0 * 5 + 10 + j], nfp[512 + m0 * 5 + 15 + j]);
    }

    // Moment accumulators (per channel-pair):
    //  [0]=b10(s0), [1..3]=b11(p), [4..5]=b20(s), [6..11]=b21(s*3+p),
    //  [12..14]=b30(s), [15..23]=b31(s*3+p)
    u64 MA[24], MB[24];
    #pragma unroll
    for (int i = 0; i < 24; i++){ MA[i] = 0ull; MB[i] = 0ull; }

    int i2 = 0, i3 = 0;                       // constant-folded by full unroll
    #pragma unroll
    for (int a = 0; a < 9; a++){
        {
            // batch both C1 loads before the fma2s
            ulonglong2 c0 = *(const ulonglong2*)(sC1 + a * 4);
            ulonglong2 c1 = *(const ulonglong2*)(sC1 + a * 4 + 2);
            fma2(MA[0], c0.x, xA[a]);  fma2(MB[0], c0.x, xB[a]);
            fma2(MA[1], c0.y, xA[a]);  fma2(MB[1], c0.y, xB[a]);
            fma2(MA[2], c1.x, xA[a]);  fma2(MB[2], c1.x, xB[a]);
            fma2(MA[3], c1.y, xA[a]);  fma2(MB[3], c1.y, xB[a]);
        }
        #pragma unroll
        for (int b = a; b < 9; b++){
            u64 pabA = mul2(xA[a], xA[b]);
            u64 pabB = mul2(xB[a], xB[b]);
            {
                // batch all 4 C2 loads (4x LDS.128) before the 16 fma2s
                ulonglong2 c0 = *(const ulonglong2*)(sC2 + i2 * 8 + 0);
                ulonglong2 c1 = *(const ulonglong2*)(sC2 + i2 * 8 + 2);
                ulonglong2 c2 = *(const ulonglong2*)(sC2 + i2 * 8 + 4);
                ulonglong2 c3 = *(const ulonglong2*)(sC2 + i2 * 8 + 6);
                fma2(MA[4],  c0.x, pabA);  fma2(MB[4],  c0.x, pabB);
                fma2(MA[5],  c0.y, pabA);  fma2(MB[5],  c0.y, pabB);
                fma2(MA[6],  c1.x, pabA);  fma2(MB[6],  c1.x, pabB);
                fma2(MA[7],  c1.y, pabA);  fma2(MB[7],  c1.y, pabB);
                fma2(MA[8],  c2.x, pabA);  fma2(MB[8],  c2.x, pabB);
                fma2(MA[9],  c2.y, pabA);  fma2(MB[9],  c2.y, pabB);
                fma2(MA[10], c3.x, pabA);  fma2(MB[10], c3.x, pabB);
                fma2(MA[11], c3.y, pabA);  fma2(MB[11], c3.y, pabB);
            }
            i2++;
            #pragma unroll
            for (int k = b; k < 9; k++){
                u64 p3A = mul2(pabA, xA[k]);
                u64 p3B = mul2(pabB, xB[k]);
                // batch all 6 C3 loads (3x LDS.128... 6 pairs = 6 u64 = 3 LDS.128)
                ulonglong2 c0 = *(const ulonglong2*)(sC3 + i3 * 12 + 0);
                ulonglong2 c1 = *(const ulonglong2*)(sC3 + i3 * 12 + 2);
                ulonglong2 c2 = *(const ulonglong2*)(sC3 + i3 * 12 + 4);
                ulonglong2 c3 = *(const ulonglong2*)(sC3 + i3 * 12 + 6);
                ulonglong2 c4 = *(const ulonglong2*)(sC3 + i3 * 12 + 8);
                ulonglong2 c5 = *(const ulonglong2*)(sC3 + i3 * 12 + 10);
                fma2(MA[12], c0.x, p3A);  fma2(MB[12], c0.x, p3B);
                fma2(MA[13], c0.y, p3A);  fma2(MB[13], c0.y, p3B);
                fma2(MA[14], c1.x, p3A);  fma2(MB[14], c1.x, p3B);
                fma2(MA[15], c1.y, p3A);  fma2(MB[15], c1.y, p3B);
                fma2(MA[16], c2.x, p3A);  fma2(MB[16], c2.x, p3B);
                fma2(MA[17], c2.y, p3A);  fma2(MB[17], c2.y, p3B);
                fma2(MA[18], c3.x, p3A);  fma2(MB[18], c3.x, p3B);
                fma2(MA[19], c3.y, p3A);  fma2(MB[19], c3.y, p3B);
                fma2(MA[20], c4.x, p3A);  fma2(MB[20], c4.x, p3B);
                fma2(MA[21], c4.y, p3A);  fma2(MB[21], c4.y, p3B);
                fma2(MA[22], c5.x, p3A);  fma2(MB[22], c5.x, p3B);
                fma2(MA[23], c5.y, p3A);  fma2(MB[23], c5.y, p3B);
                i3++;
            }
        }
    }

    // ---- combine with per-(species, channel) weights ----
    const int sp = species[node];
    float* outp = out + (size_t)node * 512;

    // slice 0 ([0,128)): both pairs -> one float4 store
    float o0[4];
    #pragma unroll
    for (int h = 0; h < 2; h++){
        const int mc = m0 + 2 * h;
        u64* M = h ? MB : MA;
        u64 o = mul2(*(const u64*)(w10 + sp * 128 + mc), M[0]);
        fma2(o, *(const u64*)(w20 + sp * 256 +   0 + mc), M[4]);
        fma2(o, *(const u64*)(w20 + sp * 256 + 128 + mc), M[5]);
        fma2(o, *(const u64*)(w30 + sp * 384 +   0 + mc), M[12]);
        fma2(o, *(const u64*)(w30 + sp * 384 + 128 + mc), M[13]);
        fma2(o, *(const u64*)(w30 + sp * 384 + 256 + mc), M[14]);
        unpack2(o, o0[2 * h], o0[2 * h + 1]);
    }
    *(float4*)(outp + m0) = make_float4(o0[0], o0[1], o0[2], o0[3]);

    // slice 1 ([128,512)): dim-3 per channel
    #pragma unroll
    for (int h = 0; h < 2; h++){
        const int mc = m0 + 2 * h;
        u64* M = h ? MB : MA;
        u64 w11v  = *(const u64*)(w11 + sp * 128 + mc);
        u64 w21s0 = *(const u64*)(w21 + sp * 256 +   0 + mc);
        u64 w21s1 = *(const u64*)(w21 + sp * 256 + 128 + mc);
        u64 w31s0 = *(const u64*)(w31 + sp * 384 +   0 + mc);
        u64 w31s1 = *(const u64*)(w31 + sp * 384 + 128 + mc);
        u64 w31s2 = *(const u64*)(w31 + sp * 384 + 256 + mc);
        #pragma unroll
        for (int p = 0; p < 3; p++){
            u64 o = mul2(w11v, M[1 + p]);
            fma2(o, w21s0, M[6 + p]);
            fma2(o, w21s1, M[9 + p]);
            fma2(o, w31s0, M[15 + p]);
            fma2(o, w31s1, M[18 + p]);
            fma2(o, w31s2, M[21 + p]);
            float lo, hi; unpack2(o, lo, hi);
            outp[128 + mc * 3 + p]     = lo;
            outp[128 + mc * 3 + 3 + p] = hi;
        }
    }
}

extern "C" void kernel_launch(void* const* d_in, const int* in_sizes, int n_in,
                              void* d_out, int out_size){
    // metadata order is INTERLEAVED (b_i, w_i) pairs.
    const float* nf      = (const float*)d_in[0];
    const int*   species = (const int*)  d_in[1];
    const float* b10 = (const float*)d_in[2];
    const float* w10 = (const float*)d_in[3];
    const float* b11 = (const float*)d_in[4];
    const float* w11 = (const float*)d_in[5];
    const float* b20 = (const float*)d_in[6];
    const float* w20 = (const float*)d_in[7];
    const float* b21 = (const float*)d_in[8];
    const float* w21 = (const float*)d_in[9];
    const float* b30 = (const float*)d_in[10];
    const float* w30 = (const float*)d_in[11];
    const float* b31 = (const float*)d_in[12];
    const float* w31 = (const float*)d_in[13];

    const int n_nodes = in_sizes[1];   // species element count (2048, even)

    prep_kernel<<<19, 128>>>(b10, b11, b20, b21, b30, b31);
    // 1 block = 2 nodes, 32 threads/node, 4 channels/thread
    mace_kernel<<<n_nodes / 2, 64>>>(nf, species, w10, w11, w20, w21, w30, w31,
                                     (float*)d_out);
}

// round 7
// speedup vs baseline: 6.5231x; 1.0406x over previous
#include <cuda_runtime.h>

typedef unsigned long long u64;

// ---------- packed f32x2 helpers (sm_103a FFMA2 only via PTX) ----------
__device__ __forceinline__ u64 pack2(float lo, float hi){
    u64 r; asm("mov.b64 %0, {%1,%2};" : "=l"(r) : "f"(lo), "f"(hi)); return r;
}
__device__ __forceinline__ void unpack2(u64 v, float &lo, float &hi){
    asm("mov.b64 {%0,%1}, %2;" : "=f"(lo), "=f"(hi) : "l"(v));
}
__device__ __forceinline__ u64 mul2(u64 a, u64 b){
    u64 r; asm("mul.rn.f32x2 %0, %1, %2;" : "=l"(r) : "l"(a), "l"(b)); return r;
}
__device__ __forceinline__ void fma2(u64 &d, u64 a, u64 b){
    asm("fma.rn.f32x2 %0, %1, %2, %0;" : "+l"(d) : "l"(a), "l"(b));
}

// ---------- symmetrized coefficient tables (written by prep each launch) ----
__device__ __align__(16) u64 g_C1[9 * 4];      // deg-1: 9 monos x 4 cols
__device__ __align__(16) u64 g_C2[45 * 8];     // deg-2: 45 monos x 8 cols
__device__ __align__(16) u64 g_C3[165 * 12];   // deg-3: 165 monos x 12 cols

__device__ __forceinline__ float fetch3(const float* __restrict__ b30,
                                        const float* __restrict__ b31,
                                        int i, int j, int k, int c){
    int base = ((i * 9 + j) * 9 + k) * 3;         // b30: (9,9,9,3,1); b31: (9,9,9,3,3)
    if (c < 3) return b30[base + c];
    return b31[base * 3 + (c - 3)];
}

__global__ void prep_kernel(const float* __restrict__ b10, const float* __restrict__ b11,
                            const float* __restrict__ b20, const float* __restrict__ b21,
                            const float* __restrict__ b30, const float* __restrict__ b31){
    int tid = blockIdx.x * blockDim.x + threadIdx.x;

    if (tid < 36){
        int a = tid >> 2, c = tid & 3;
        float v = (c == 0) ? b10[a] : b11[a * 3 + c - 1];
        g_C1[tid] = pack2(v, v);
    }

    int t2 = tid - 64;
    if (t2 >= 0 && t2 < 45 * 8){
        int mono = t2 >> 3, c = t2 & 7;
        int a = 0, rem = mono;
        while (rem >= 9 - a){ rem -= 9 - a; a++; }
        int b = a + rem;                            // a <= b
        float v;
        if (c < 2){                                 // b20: (9,9,2,1)
            v = b20[(a * 9 + b) * 2 + c];
            if (a != b) v += b20[(b * 9 + a) * 2 + c];
        } else {                                    // b21: (9,9,2,3); c-2 = s*3+p
            int sp = c - 2;
            v = b21[(a * 9 + b) * 6 + sp];
            if (a != b) v += b21[(b * 9 + a) * 6 + sp];
        }
        g_C2[t2] = pack2(v, v);
    }

    int t3 = tid - 448;
    if (t3 >= 0 && t3 < 165 * 12){
        int mono = t3 / 12, c = t3 % 12;
        int a = 0, rem = mono;
        while (true){ int cnt = (9 - a) * (10 - a) / 2; if (rem < cnt) break; rem -= cnt; a++; }
        int b = a;
        while (rem >= 9 - b){ rem -= 9 - b; b++; }
        int k = b + rem;                            // a <= b <= k
        float v = fetch3(b30, b31, a, b, k, c);
        if (a == b && b == k){
        } else if (a == b){
            v += fetch3(b30, b31, a, k, b, c) + fetch3(b30, b31, k, a, b, c);
        } else if (b == k){
            v += fetch3(b30, b31, b, a, k, c) + fetch3(b30, b31, b, k, a, c);
        } else {
            v += fetch3(b30, b31, a, k, b, c) + fetch3(b30, b31, b, a, k, c)
               + fetch3(b30, b31, b, k, a, c) + fetch3(b30, b31, k, a, b, c)
               + fetch3(b30, b31, k, b, a, c);
        }
        g_C3[t3] = pack2(v, v);
    }
}

// ---------- main kernel ------------------------------------------------------
// 1 block = 2 nodes, 128 threads. Per node: 64 threads; lane pair (2q, 2q+1)
// covers channel quad m0=4q, split by output-column half (colHalf = lane&1):
//   colHalf 0 -> C1 cols 0,1 | C2 cols 0..3 | C3 cols 0..5
//   colHalf 1 -> C1 cols 2,3 | C2 cols 4..7 | C3 cols 6..11
// Moment accumulators per thread: 12 cols x 2 ch-pairs = 24 u64 (48 regs).
// Pair-reduction via warp shuffles at the end.
__global__ void __launch_bounds__(128) mace_kernel(
    const float* __restrict__ nf, const int* __restrict__ species,
    const float* __restrict__ w10, const float* __restrict__ w11,
    const float* __restrict__ w20, const float* __restrict__ w21,
    const float* __restrict__ w30, const float* __restrict__ w31,
    float* __restrict__ out)
{
    __shared__ __align__(16) u64 sC1[9 * 4];
    __shared__ __align__(16) u64 sC2[45 * 8];
    __shared__ __align__(16) u64 sC3[165 * 12];

    const int t = threadIdx.x;
    for (int i = t; i < 36;   i += 128) sC1[i] = g_C1[i];
    for (int i = t; i < 360;  i += 128) sC2[i] = g_C2[i];
    for (int i = t; i < 1980; i += 128) sC3[i] = g_C3[i];
    __syncthreads();

    const int node    = blockIdx.x * 2 + (t >> 6);
    const int tl      = t & 63;
    const int q       = tl >> 1;          // channel quad index [0,32)
    const int colHalf = tl & 1;           // which half of output columns
    const int m0      = q * 4;            // channels m0..m0+3 (pair A, pair B)
    const float* nfp  = nf + (size_t)node * 1152;

    // x components fully in registers.
    u64 xA[9], xB[9];
    {
        float4 v = *(const float4*)(nfp + m0);
        xA[0] = pack2(v.x, v.y);
        xB[0] = pack2(v.z, v.w);
    }
    #pragma unroll
    for (int j = 0; j < 3; j++){
        xA[1 + j] = pack2(nfp[128 + m0 * 3 + j],      nfp[128 + m0 * 3 + 3 + j]);
        xB[1 + j] = pack2(nfp[128 + m0 * 3 + 6 + j],  nfp[128 + m0 * 3 + 9 + j]);
    }
    #pragma unroll
    for (int j = 0; j < 5; j++){
        xA[4 + j] = pack2(nfp[512 + m0 * 5 + j],      nfp[512 + m0 * 5 + 5 + j]);
        xB[4 + j] = pack2(nfp[512 + m0 * 5 + 10 + j], nfp[512 + m0 * 5 + 15 + j]);
    }

    // Per-thread moment accumulators for this column half:
    //  P*[0..1]  = C1 cols (colHalf*2 +0..1)
    //  P*[2..5]  = C2 cols (colHalf*4 +0..3)
    //  P*[6..11] = C3 cols (colHalf*6 +0..5)
    u64 PA[12], PB[12];
    #pragma unroll
    for (int i = 0; i < 12; i++){ PA[i] = 0ull; PB[i] = 0ull; }

    const int o1 = colHalf * 2;   // C1 column offset (u64)
    const int o2 = colHalf * 4;   // C2 column offset
    const int o3 = colHalf * 6;   // C3 column offset

    int i2 = 0, i3 = 0;                       // constant-folded by full unroll
    #pragma unroll
    for (int a = 0; a < 9; a++){
        {
            ulonglong2 c0 = *(const ulonglong2*)(sC1 + a * 4 + o1);
            fma2(PA[0], c0.x, xA[a]);  fma2(PB[0], c0.x, xB[a]);
            fma2(PA[1], c0.y, xA[a]);  fma2(PB[1], c0.y, xB[a]);
        }
        #pragma unroll
        for (int b = a; b < 9; b++){
            u64 pabA = mul2(xA[a], xA[b]);
            u64 pabB = mul2(xB[a], xB[b]);
            {
                ulonglong2 c0 = *(const ulonglong2*)(sC2 + i2 * 8 + o2);
                ulonglong2 c1 = *(const ulonglong2*)(sC2 + i2 * 8 + o2 + 2);
                fma2(PA[2], c0.x, pabA);  fma2(PB[2], c0.x, pabB);
                fma2(PA[3], c0.y, pabA);  fma2(PB[3], c0.y, pabB);
                fma2(PA[4], c1.x, pabA);  fma2(PB[4], c1.x, pabB);
                fma2(PA[5], c1.y, pabA);  fma2(PB[5], c1.y, pabB);
            }
            i2++;
            #pragma unroll
            for (int k = b; k < 9; k++){
                u64 p3A = mul2(pabA, xA[k]);
                u64 p3B = mul2(pabB, xB[k]);
                ulonglong2 c0 = *(const ulonglong2*)(sC3 + i3 * 12 + o3);
                ulonglong2 c1 = *(const ulonglong2*)(sC3 + i3 * 12 + o3 + 2);
                ulonglong2 c2 = *(const ulonglong2*)(sC3 + i3 * 12 + o3 + 4);
                fma2(PA[6],  c0.x, p3A);  fma2(PB[6],  c0.x, p3B);
                fma2(PA[7],  c0.y, p3A);  fma2(PB[7],  c0.y, p3B);
                fma2(PA[8],  c1.x, p3A);  fma2(PB[8],  c1.x, p3B);
                fma2(PA[9],  c1.y, p3A);  fma2(PB[9],  c1.y, p3B);
                fma2(PA[10], c2.x, p3A);  fma2(PB[10], c2.x, p3B);
                fma2(PA[11], c2.y, p3A);  fma2(PB[11], c2.y, p3B);
                i3++;
            }
        }
    }

    // ---- fold with per-(species, channel) weights into output accumulators --
    const int sp = species[node];
    const float* W10 = w10 + sp * 128;
    const float* W11 = w11 + sp * 128;
    const float* W20 = w20 + sp * 256;
    const float* W21 = w21 + sp * 256;
    const float* W30 = w30 + sp * 384;
    const float* W31 = w31 + sp * 384;

    // Output accumulators per ch-pair: O0 (scalar slice), OP0..2 (vector slice)
    u64 O0[2]  = {0ull, 0ull};
    u64 OP0[2] = {0ull, 0ull}, OP1[2] = {0ull, 0ull}, OP2[2] = {0ull, 0ull};

    #pragma unroll
    for (int h = 0; h < 2; h++){
        const int mc = m0 + 2 * h;
        u64* P = h ? PB : PA;
        if (colHalf == 0){
            // C1 c0 -> O0 (w10); c1 -> OP0 (w11)
            fma2(O0[h],  *(const u64*)(W10 + mc),       P[0]);
            fma2(OP0[h], *(const u64*)(W11 + mc),       P[1]);
            // C2 c0,c1 -> O0 (w20 s0,s1); c2 -> OP0 (w21 s0); c3 -> OP1 (w21 s0)
            fma2(O0[h],  *(const u64*)(W20 + mc),       P[2]);
            fma2(O0[h],  *(const u64*)(W20 + 128 + mc), P[3]);
            fma2(OP0[h], *(const u64*)(W21 + mc),       P[4]);
            fma2(OP1[h], *(const u64*)(W21 + mc),       P[5]);
            // C3 c0..2 -> O0 (w30 s0..2); c3..5 -> OP0..2 (w31 s0)
            fma2(O0[h],  *(const u64*)(W30 + mc),       P[6]);
            fma2(O0[h],  *(const u64*)(W30 + 128 + mc), P[7]);
            fma2(O0[h],  *(const u64*)(W30 + 256 + mc), P[8]);
            fma2(OP0[h], *(const u64*)(W31 + mc),       P[9]);
            fma2(OP1[h], *(const u64*)(W31 + mc),       P[10]);
            fma2(OP2[h], *(const u64*)(W31 + mc),       P[11]);
        } else {
            // C1 c2,c3 = b11 p1,p2 -> OP1, OP2 (w11)
            fma2(OP1[h], *(const u64*)(W11 + mc),       P[0]);
            fma2(OP2[h], *(const u64*)(W11 + mc),       P[1]);
            // C2 c4 = s0p2 -> OP2 (w21 s0); c5..7 = s1 p0..2 -> OP0..2 (w21 s1)
            fma2(OP2[h], *(const u64*)(W21 + mc),       P[2]);
            fma2(OP0[h], *(const u64*)(W21 + 128 + mc), P[3]);
            fma2(OP1[h], *(const u64*)(W21 + 128 + mc), P[4]);
            fma2(OP2[h], *(const u64*)(W21 + 128 + mc), P[5]);
            // C3 c6..8 = s1 p0..2 -> OP0..2 (w31 s1); c9..11 = s2 p0..2 (w31 s2)
            fma2(OP0[h], *(const u64*)(W31 + 128 + mc), P[6]);
            fma2(OP1[h], *(const u64*)(W31 + 128 + mc), P[7]);
            fma2(OP2[h], *(const u64*)(W31 + 128 + mc), P[8]);
            fma2(OP0[h], *(const u64*)(W31 + 256 + mc), P[9]);
            fma2(OP1[h], *(const u64*)(W31 + 256 + mc), P[10]);
            fma2(OP2[h], *(const u64*)(W31 + 256 + mc), P[11]);
        }
    }

    // ---- pair reduction (lane 2q gets lane 2q+1's partials) and store -------
    float* outp = out + (size_t)node * 512;

    float r[16];  // [h][acc: O0,OP0,OP1,OP2][lo/hi]
    #pragma unroll
    for (int h = 0; h < 2; h++){
        unpack2(O0[h],  r[h*8+0], r[h*8+1]);
        unpack2(OP0[h], r[h*8+2], r[h*8+3]);
        unpack2(OP1[h], r[h*8+4], r[h*8+5]);
        unpack2(OP2[h], r[h*8+6], r[h*8+7]);
    }
    #pragma unroll
    for (int i = 0; i < 16; i++)
        r[i] += __shfl_down_sync(0xFFFFFFFFu, r[i], 1);

    if (colHalf == 0){
        // slice 0 ([0,128)): channels m0..m0+3
        *(float4*)(outp + m0) = make_float4(r[0], r[1], r[8], r[9]);
        // slice 1 ([128,512)): per channel 3 components
        #pragma unroll
        for (int h = 0; h < 2; h++){
            const int mc = m0 + 2 * h;
            outp[128 + mc * 3 + 0] = r[h*8+2];  outp[128 + mc * 3 + 3] = r[h*8+3];
            outp[128 + mc * 3 + 1] = r[h*8+4];  outp[128 + mc * 3 + 4] = r[h*8+5];
            outp[128 + mc * 3 + 2] = r[h*8+6];  outp[128 + mc * 3 + 5] = r[h*8+7];
        }
    }
}

extern "C" void kernel_launch(void* const* d_in, const int* in_sizes, int n_in,
                              void* d_out, int out_size){
    // metadata order is INTERLEAVED (b_i, w_i) pairs.
    const float* nf      = (const float*)d_in[0];
    const int*   species = (const int*)  d_in[1];
    const float* b10 = (const float*)d_in[2];
    const float* w10 = (const float*)d_in[3];
    const float* b11 = (const float*)d_in[4];
    const float* w11 = (const float*)d_in[5];
    const float* b20 = (const float*)d_in[6];
    const float* w20 = (const float*)d_in[7];
    const float* b21 = (const float*)d_in[8];
    const float* w21 = (const float*)d_in[9];
    const float* b30 = (const float*)d_in[10];
    const float* w30 = (const float*)d_in[11];
    const float* b31 = (const float*)d_in[12];
    const float* w31 = (const float*)d_in[13];

    const int n_nodes = in_sizes[1];   // species element count (2048, even)

    prep_kernel<<<19, 128>>>(b10, b11, b20, b21, b30, b31);
    // 1 block = 2 nodes, 64 threads/node (lane pairs split output columns)
    mace_kernel<<<n_nodes / 2, 128>>>(nf, species, w10, w11, w20, w21, w30, w31,
                                      (float*)d_out);
}